// round 1
// baseline (speedup 1.0000x reference)
#include <cuda_runtime.h>
#include <cstdint>
#include <math_constants.h>

#define TOKENS  16384      // B*S = 4*4096
#define HDIM    4096
#define NEXP    64
#define MT      128        // tokens per block
#define KB      32         // k per tile
#define NKT     (HDIM / KB)
#define NTHREADS 256

__device__ __forceinline__ void cp_async16(void* sdst, const void* gsrc) {
    uint32_t s = (uint32_t)__cvta_generic_to_shared(sdst);
    asm volatile("cp.async.cg.shared.global [%0], [%1], 16;\n"
                 :: "r"(s), "l"(gsrc) : "memory");
}
__device__ __forceinline__ void cp_commit() {
    asm volatile("cp.async.commit_group;\n" ::: "memory");
}
__device__ __forceinline__ void cp_wait_all() {
    asm volatile("cp.async.wait_group 0;\n" ::: "memory");
}

// smem layout (48KB total, reused by epilogue):
//   As[2][128][32]  floats  [0      .. 8192)
//   Bs[2][32][64]   floats  [8192   .. 12288)   (k-major so compute loads are float4 over experts)
//   epilogue logits L[128][65]  (padded stride 65 -> conflict-free row scans)
__global__ __launch_bounds__(NTHREADS)
void molora_router_kernel(const float* __restrict__ x,
                          const float* __restrict__ w,
                          float* __restrict__ out)
{
    __shared__ float smem[12288];
    float* As = smem;           // [2][MT][KB]
    float* Bs = smem + 8192;    // [2][KB][NEXP]

    const int tid = threadIdx.x;
    const int m0  = blockIdx.x * MT;
    const int ty  = tid >> 4;   // 0..15 -> 8 tokens each
    const int tx  = tid & 15;   // 0..15 -> 4 experts each

    // A global-load mapping: lanes 0..7 cover one 128B row segment (coalesced)
    const int kq   = tid & 7;   // float4 index within KB
    const int mrow = tid >> 3;  // 0..31, plus strides of 32
    // B global-load mapping
    const int be = tid & 63;          // expert
    const int bk = (tid >> 6) << 2;   // 0,4,8,12 (plus +16 for second half)

    float acc[8][4];
#pragma unroll
    for (int i = 0; i < 8; i++)
#pragma unroll
        for (int j = 0; j < 4; j++) acc[i][j] = 0.0f;

    const float* xg  = x + (size_t)(m0 + mrow) * HDIM + kq * 4;
    const float* wg0 = w + (size_t)be * HDIM + bk;
    const float* wg1 = wg0 + 16;

    // ---- prologue: tile 0 -> buffer 0 ----
    {
#pragma unroll
        for (int p = 0; p < 4; p++)
            cp_async16(&As[(mrow + 32 * p) * KB + kq * 4], xg + (size_t)(32 * p) * HDIM);
        cp_commit();
        float4 b0 = *(const float4*)wg0;
        float4 b1 = *(const float4*)wg1;
        cp_wait_all();
#pragma unroll
        for (int j = 0; j < 4; j++) {
            Bs[(bk + j)      * NEXP + be] = ((const float*)&b0)[j];
            Bs[(bk + 16 + j) * NEXP + be] = ((const float*)&b1)[j];
        }
        __syncthreads();
    }

    // ---- main K loop, double buffered ----
    for (int kt = 0; kt < NKT; kt++) {
        const int cur = kt & 1;
        const int nxt = cur ^ 1;
        float4 nb0, nb1;
        const bool has_next = (kt + 1 < NKT);
        if (has_next) {
            const float* xn = xg + (size_t)(kt + 1) * KB;
#pragma unroll
            for (int p = 0; p < 4; p++)
                cp_async16(&As[nxt * 4096 + (mrow + 32 * p) * KB + kq * 4],
                           xn + (size_t)(32 * p) * HDIM);
            cp_commit();
            nb0 = *(const float4*)(wg0 + (size_t)(kt + 1) * KB);
            nb1 = *(const float4*)(wg1 + (size_t)(kt + 1) * KB);
        }

        // ---- compute on current buffer ----
        const float* Ab = As + cur * 4096 + (ty * 8) * KB;
        const float* Bb = Bs + cur * 2048 + tx * 4;
#pragma unroll
        for (int k4 = 0; k4 < KB / 4; k4++) {
            float4 b0 = *(const float4*)&Bb[(k4 * 4 + 0) * NEXP];
            float4 b1 = *(const float4*)&Bb[(k4 * 4 + 1) * NEXP];
            float4 b2 = *(const float4*)&Bb[(k4 * 4 + 2) * NEXP];
            float4 b3 = *(const float4*)&Bb[(k4 * 4 + 3) * NEXP];
#pragma unroll
            for (int i = 0; i < 8; i++) {
                float4 a = *(const float4*)&Ab[i * KB + k4 * 4];
                acc[i][0] = fmaf(a.x, b0.x, acc[i][0]);
                acc[i][0] = fmaf(a.y, b1.x, acc[i][0]);
                acc[i][0] = fmaf(a.z, b2.x, acc[i][0]);
                acc[i][0] = fmaf(a.w, b3.x, acc[i][0]);
                acc[i][1] = fmaf(a.x, b0.y, acc[i][1]);
                acc[i][1] = fmaf(a.y, b1.y, acc[i][1]);
                acc[i][1] = fmaf(a.z, b2.y, acc[i][1]);
                acc[i][1] = fmaf(a.w, b3.y, acc[i][1]);
                acc[i][2] = fmaf(a.x, b0.z, acc[i][2]);
                acc[i][2] = fmaf(a.y, b1.z, acc[i][2]);
                acc[i][2] = fmaf(a.z, b2.z, acc[i][2]);
                acc[i][2] = fmaf(a.w, b3.z, acc[i][2]);
                acc[i][3] = fmaf(a.x, b0.w, acc[i][3]);
                acc[i][3] = fmaf(a.y, b1.w, acc[i][3]);
                acc[i][3] = fmaf(a.z, b2.w, acc[i][3]);
                acc[i][3] = fmaf(a.w, b3.w, acc[i][3]);
            }
        }

        if (has_next) {
#pragma unroll
            for (int j = 0; j < 4; j++) {
                Bs[nxt * 2048 + (bk + j)      * NEXP + be] = ((const float*)&nb0)[j];
                Bs[nxt * 2048 + (bk + 16 + j) * NEXP + be] = ((const float*)&nb1)[j];
            }
            cp_wait_all();   // waits for the group issued at top of this iter
        }
        __syncthreads();
    }

    // ---- epilogue: top-2 softmax renorm per token ----
    // Dump logits into smem [128][65] (stride 65 -> conflict-free scans)
    float* L = smem;
#pragma unroll
    for (int i = 0; i < 8; i++)
#pragma unroll
        for (int j = 0; j < 4; j++)
            L[(ty * 8 + i) * 65 + tx * 4 + j] = acc[i][j];
    __syncthreads();

    if (tid < MT) {
        const float* row = L + tid * 65;
        float best1 = -CUDART_INF_F, best2 = -CUDART_INF_F;
        int i1 = 0, i2 = 0;
#pragma unroll
        for (int e = 0; e < NEXP; e++) {
            float v = row[e];
            if (v > best1) { best2 = best1; i2 = i1; best1 = v; i1 = e; }
            else if (v > best2) { best2 = v; i2 = e; }
        }
        float s   = expf(best2 - best1);     // <= 1
        float inv = 1.0f / (1.0f + s);
        float w1  = inv;
        float w2  = s * inv;

        const int gt = m0 + tid;
        // weights first (B*S*2 floats), then indices cast to float
        out[2 * gt + 0] = w1;
        out[2 * gt + 1] = w2;
        out[(size_t)TOKENS * 2 + 2 * gt + 0] = (float)i1;
        out[(size_t)TOKENS * 2 + 2 * gt + 1] = (float)i2;
    }
}

extern "C" void kernel_launch(void* const* d_in, const int* in_sizes, int n_in,
                              void* d_out, int out_size)
{
    const float* x = (const float*)d_in[0];      // [4,4096,4096] f32
    const float* w = (const float*)d_in[1];      // [64,4096]     f32
    float* out = (float*)d_out;                  // [2*16384 weights | 2*16384 indices]

    (void)in_sizes; (void)n_in; (void)out_size;

    dim3 grid(TOKENS / MT);   // 128 CTAs
    dim3 block(NTHREADS);
    molora_router_kernel<<<grid, block>>>(x, w, out);
}